// round 7
// baseline (speedup 1.0000x reference)
#include <cuda_runtime.h>
#include <cuda_fp16.h>
#include <stdint.h>

// x: (4, 2048, 128 + 4096) fp32
// Output buffer is ONE float32 array (numpy concat promotion of int8/fp16/fp32):
//   q       : [8192*4096] floats  at offset 0          (integer values -8..7)
//   scales  : [8192]      floats  at offset 33554432
//   outlier : [8192*128]  floats  at offset 33562624

#define POD      128
#define HIDDEN   4096
#define ROWLEN   (POD + HIDDEN)      // 4224 floats per row
#define NROWS    8192
#define NTHREADS 256
#define NWARPS   (NTHREADS / 32)
#define RPC      4                   // rows per CTA (software pipeline depth)
#define NBLOCKS  (NROWS / RPC)       // 2048
#define Q_ELEMS  ((size_t)NROWS * HIDDEN)   // 33554432
#define S_ELEMS  ((size_t)NROWS)            // 8192

struct RowBuf { float4 v[4]; };

__device__ __forceinline__ void load_row(const float* __restrict__ x, int r, int t,
                                         RowBuf& b)
{
    const float4* main4 = (const float4*)(x + (size_t)r * ROWLEN + POD);
#pragma unroll
    for (int i = 0; i < 4; i++)
        b.v[i] = __ldcs(&main4[t + i * NTHREADS]);
}

__global__ __launch_bounds__(NTHREADS, 4)
void quantizer_tl_kernel(const float* __restrict__ x,
                         float* __restrict__ q_out,
                         float* __restrict__ s_out,
                         float* __restrict__ o_out)
{
    const int t   = threadIdx.x;
    const int wid = t >> 5;
    const int lid = t & 31;
    const int r0  = blockIdx.x * RPC;

    __shared__ float wmax[2][NWARPS];

    RowBuf cur, nxt;
    load_row(x, r0, t, cur);

#pragma unroll
    for (int k = 0; k < RPC; k++) {
        const int r = r0 + k;

        // ---- prefetch next row BEFORE this row's barrier (overlaps bubble+stores) ----
        if (k + 1 < RPC) load_row(x, r + 1, t, nxt);

        // ---- outlier copy: 32 float4 spread one-slice-per-warp ----
        if (lid < 4) {
            const int j = wid * 4 + lid;
            float4 ov = __ldcs(&((const float4*)(x + (size_t)r * ROWLEN))[j]);
            __stcs(&((float4*)(o_out + (size_t)r * POD))[j], ov);
        }

        // ---- local absmax ----
        float amax = 0.0f;
#pragma unroll
        for (int i = 0; i < 4; i++)
            amax = fmaxf(amax,
                   fmaxf(fmaxf(fabsf(cur.v[i].x), fabsf(cur.v[i].y)),
                         fmaxf(fabsf(cur.v[i].z), fabsf(cur.v[i].w))));

        // warp max (non-negative fp32 orders as u32)
        amax = __uint_as_float(__reduce_max_sync(0xffffffffu, __float_as_uint(amax)));
        if (lid == 0) wmax[k & 1][wid] = amax;
        __syncthreads();

        float m = wmax[k & 1][0];
#pragma unroll
        for (int i = 1; i < NWARPS; i++) m = fmaxf(m, wmax[k & 1][i]);

        // scales = fp16(absmax / 7.0) * fp16(1.0)  (CLIP=1.0 identity in fp16)
        const __half h  = __float2half(m * (1.0f / 7.0f));
        const float  s  = __half2float(h);
        const float inv = 1.0f / s;
        if (t == 0) s_out[r] = s;

        // ---- quantize; refined division == fp32 v/s (bitwise exact) ----
        float4* q4 = (float4*)(q_out + (size_t)r * HIDDEN);
#pragma unroll
        for (int i = 0; i < 4; i++) {
            float4 c;
            {
                float q0 = cur.v[i].x * inv;
                q0 = fmaf(fmaf(-q0, s, cur.v[i].x), inv, q0);
                c.x = fminf(fmaxf(rintf(q0), -8.0f), 7.0f);
            }
            {
                float q0 = cur.v[i].y * inv;
                q0 = fmaf(fmaf(-q0, s, cur.v[i].y), inv, q0);
                c.y = fminf(fmaxf(rintf(q0), -8.0f), 7.0f);
            }
            {
                float q0 = cur.v[i].z * inv;
                q0 = fmaf(fmaf(-q0, s, cur.v[i].z), inv, q0);
                c.z = fminf(fmaxf(rintf(q0), -8.0f), 7.0f);
            }
            {
                float q0 = cur.v[i].w * inv;
                q0 = fmaf(fmaf(-q0, s, cur.v[i].w), inv, q0);
                c.w = fminf(fmaxf(rintf(q0), -8.0f), 7.0f);
            }
            __stcs(&q4[t + i * NTHREADS], c);
        }

        cur = nxt;   // register rename under full unroll
    }
}

extern "C" void kernel_launch(void* const* d_in, const int* in_sizes, int n_in,
                              void* d_out, int out_size)
{
    (void)in_sizes; (void)n_in; (void)out_size;
    const float* x = (const float*)d_in[0];

    float* out = (float*)d_out;
    float* q   = out;
    float* s   = out + Q_ELEMS;
    float* o   = out + Q_ELEMS + S_ELEMS;

    quantizer_tl_kernel<<<NBLOCKS, NTHREADS>>>(x, q, s, o);
}